// round 1
// baseline (speedup 1.0000x reference)
#include <cuda_runtime.h>
#include <math.h>

// Problem dims
#define BS_  2
#define SEQ  2048
#define DIM  1024
#define NH   16
#define DHD  64
#define DFF  4096
#define MROWS (BS_*SEQ)   // 4096

// ---------------- Scratch (device globals; no allocation in kernel_launch) ----
__device__ float g_x  [MROWS * DIM];      // ln1 out
__device__ float g_qkv[MROWS * 3 * DIM];  // qkv
__device__ float g_att[MROWS * DIM];      // attention out (pre-proj)
__device__ float g_h  [MROWS * DIM];      // residual 2 input
__device__ float g_y  [MROWS * DIM];      // ln2 out
__device__ float g_fc [MROWS * DFF];      // fc (gelu'd)

// ---------------- LayerNorm: one block per row of 1024 ------------------------
__global__ void __launch_bounds__(256)
ln_kernel(const float* __restrict__ in, const float* __restrict__ w,
          const float* __restrict__ b, float* __restrict__ out)
{
    int row = blockIdx.x;
    int t = threadIdx.x;
    const float4* ip = (const float4*)(in + (size_t)row * DIM);
    float4 x = ip[t];
    float s  = x.x + x.y + x.z + x.w;
    float ss = x.x*x.x + x.y*x.y + x.z*x.z + x.w*x.w;
    #pragma unroll
    for (int off = 16; off; off >>= 1) {
        s  += __shfl_xor_sync(0xFFFFFFFFu, s,  off);
        ss += __shfl_xor_sync(0xFFFFFFFFu, ss, off);
    }
    __shared__ float sh_s[8], sh_ss[8];
    int wid = t >> 5, lid = t & 31;
    if (lid == 0) { sh_s[wid] = s; sh_ss[wid] = ss; }
    __syncthreads();
    float S = 0.f, SS = 0.f;
    #pragma unroll
    for (int i = 0; i < 8; i++) { S += sh_s[i]; SS += sh_ss[i]; }
    float mean = S * (1.0f / DIM);
    float var  = SS * (1.0f / DIM) - mean * mean;
    float inv  = rsqrtf(var + 1e-6f);
    float4 wv = ((const float4*)w)[t];
    float4 bv = ((const float4*)b)[t];
    float4 r;
    r.x = (x.x - mean) * inv * wv.x + bv.x;
    r.y = (x.y - mean) * inv * wv.y + bv.y;
    r.z = (x.z - mean) * inv * wv.z + bv.z;
    r.w = (x.w - mean) * inv * wv.w + bv.w;
    ((float4*)(out + (size_t)row * DIM))[t] = r;
}

// ---------------- GELU (GPT-2 tanh approx) ------------------------------------
__device__ __forceinline__ float gelu_f(float x) {
    float x3 = x * x * x;
    return 0.5f * x * (1.0f + tanhf(0.7978845608028654f * (x + 0.044715f * x3)));
}

// ---------------- Tiled fp32 GEMM: C[M,N] = A[M,K] @ B[K,N] + bias (+epilogue)
// 128x128 block tile, 256 threads, 8x8 per thread, K-step 8.
// EPI: 0 = bias only; 1 = bias + gelu; 2 = bias + residual add
template<int EPI>
__global__ void __launch_bounds__(256)
gemm_kernel(const float* __restrict__ A, const float* __restrict__ B,
            const float* __restrict__ bias, const float* __restrict__ res,
            float* __restrict__ C, int M, int N, int K)
{
    __shared__ float As[8][128];
    __shared__ float Bs[8][128];

    int t  = threadIdx.x;
    int tx = t & 15, ty = t >> 4;
    int col0 = blockIdx.x * 128;
    int row0 = blockIdx.y * 128;

    float acc[8][8];
    #pragma unroll
    for (int i = 0; i < 8; i++)
        #pragma unroll
        for (int j = 0; j < 8; j++) acc[i][j] = 0.f;

    int arow = t >> 1, ak0 = (t & 1) * 4;     // 128 rows x 8 k, 4 floats/thread
    int brow = t >> 5, bcol = (t & 31) * 4;   // 8 rows x 128 cols
    const float* Aptr = A + (size_t)(row0 + arow) * K + ak0;
    const float* Bptr = B + (size_t)brow * N + col0 + bcol;

    for (int k0 = 0; k0 < K; k0 += 8) {
        float4 av = *(const float4*)(Aptr + k0);
        float4 bv = *(const float4*)(Bptr + (size_t)k0 * N);
        As[ak0 + 0][arow] = av.x;
        As[ak0 + 1][arow] = av.y;
        As[ak0 + 2][arow] = av.z;
        As[ak0 + 3][arow] = av.w;
        *(float4*)&Bs[brow][bcol] = bv;
        __syncthreads();

        #pragma unroll
        for (int kk = 0; kk < 8; kk++) {
            float4 a0 = *(const float4*)&As[kk][ty * 8];
            float4 a1 = *(const float4*)&As[kk][ty * 8 + 4];
            float4 b0 = *(const float4*)&Bs[kk][tx * 8];
            float4 b1 = *(const float4*)&Bs[kk][tx * 8 + 4];
            float a[8] = {a0.x, a0.y, a0.z, a0.w, a1.x, a1.y, a1.z, a1.w};
            float b[8] = {b0.x, b0.y, b0.z, b0.w, b1.x, b1.y, b1.z, b1.w};
            #pragma unroll
            for (int i = 0; i < 8; i++)
                #pragma unroll
                for (int j = 0; j < 8; j++)
                    acc[i][j] += a[i] * b[j];
        }
        __syncthreads();
    }

    #pragma unroll
    for (int i = 0; i < 8; i++) {
        int r = row0 + ty * 8 + i;
        #pragma unroll
        for (int j = 0; j < 8; j += 4) {
            int c = col0 + tx * 8 + j;
            float4 v;
            v.x = acc[i][j + 0] + bias[c + 0];
            v.y = acc[i][j + 1] + bias[c + 1];
            v.z = acc[i][j + 2] + bias[c + 2];
            v.w = acc[i][j + 3] + bias[c + 3];
            if (EPI == 1) {
                v.x = gelu_f(v.x); v.y = gelu_f(v.y);
                v.z = gelu_f(v.z); v.w = gelu_f(v.w);
            } else if (EPI == 2) {
                const float4 rv = *(const float4*)&res[(size_t)r * N + c];
                v.x += rv.x; v.y += rv.y; v.z += rv.z; v.w += rv.w;
            }
            *(float4*)&C[(size_t)r * N + c] = v;
        }
    }
}

// ---------------- Flash attention (causal): one thread per query ---------------
// grid = (S/64, B*H), block = 64 threads. K/V tiles of 64 in SMEM.
// qkv layout: [B*S, 3*D], q at +h*64, k at +D+h*64, v at +2D+h*64.
__global__ void __launch_bounds__(64)
attn_kernel(const float* __restrict__ qkv, float* __restrict__ out)
{
    __shared__ float ks[64][64];
    __shared__ float vs[64][64];

    int t = threadIdx.x;
    int qtile = blockIdx.x;
    int bh = blockIdx.y;
    int b = bh >> 4, h = bh & 15;
    int qg = qtile * 64 + t;   // query position in sequence

    size_t qbase = (size_t)(b * SEQ + qg) * (3 * DIM) + h * DHD;
    float q[64], o[64];
    #pragma unroll
    for (int d = 0; d < 64; d++) {
        q[d] = qkv[qbase + d] * 0.125f;   // 1/sqrt(64)
        o[d] = 0.f;
    }
    float m = -1e30f, l = 0.f;

    for (int kt = 0; kt <= qtile; kt++) {
        const float* kbase = qkv + (size_t)(b * SEQ + kt * 64) * (3 * DIM) + DIM + h * DHD;
        const float* vbase = kbase + DIM;
        #pragma unroll 4
        for (int r = 0; r < 64; r++) {
            ks[r][t] = kbase[(size_t)r * (3 * DIM) + t];
            vs[r][t] = vbase[(size_t)r * (3 * DIM) + t];
        }
        __syncthreads();

        #pragma unroll 1
        for (int sub = 0; sub < 4; sub++) {
            float s[16];
            float mx = -1e30f;
            #pragma unroll
            for (int jj = 0; jj < 16; jj++) {
                int j = sub * 16 + jj;
                float accs = 0.f;
                const float4* kp = (const float4*)&ks[j][0];
                #pragma unroll
                for (int d4 = 0; d4 < 16; d4++) {
                    float4 kv = kp[d4];
                    accs += q[d4*4+0]*kv.x + q[d4*4+1]*kv.y
                          + q[d4*4+2]*kv.z + q[d4*4+3]*kv.w;
                }
                if (kt * 64 + j > qg) accs = -1e30f;  // causal mask (exp underflows to 0, == ref -10000 bias)
                s[jj] = accs;
                mx = fmaxf(mx, accs);
            }
            float newm = fmaxf(m, mx);
            float alpha = __expf(m - newm);
            m = newm;
            l *= alpha;
            #pragma unroll
            for (int d = 0; d < 64; d++) o[d] *= alpha;
            #pragma unroll
            for (int jj = 0; jj < 16; jj++) {
                float p = __expf(s[jj] - m);
                l += p;
                const float4* vp = (const float4*)&vs[sub * 16 + jj][0];
                #pragma unroll
                for (int d4 = 0; d4 < 16; d4++) {
                    float4 vv = vp[d4];
                    o[d4*4+0] += p * vv.x;
                    o[d4*4+1] += p * vv.y;
                    o[d4*4+2] += p * vv.z;
                    o[d4*4+3] += p * vv.w;
                }
            }
        }
        __syncthreads();
    }

    float invl = 1.0f / l;
    size_t obase = (size_t)(b * SEQ + qg) * DIM + h * DHD;
    #pragma unroll
    for (int d4 = 0; d4 < 16; d4++) {
        float4 v;
        v.x = o[d4*4+0] * invl;
        v.y = o[d4*4+1] * invl;
        v.z = o[d4*4+2] * invl;
        v.w = o[d4*4+3] * invl;
        *(float4*)&out[obase + d4 * 4] = v;
    }
}

// ---------------- Launch -------------------------------------------------------
extern "C" void kernel_launch(void* const* d_in, const int* in_sizes, int n_in,
                              void* d_out, int out_size)
{
    const float* hidden    = (const float*)d_in[0];
    const float* w_attn    = (const float*)d_in[1];
    const float* b_attn    = (const float*)d_in[2];
    const float* w_proj    = (const float*)d_in[3];
    const float* b_proj    = (const float*)d_in[4];
    const float* w_fc      = (const float*)d_in[5];
    const float* b_fc      = (const float*)d_in[6];
    const float* w_fc_proj = (const float*)d_in[7];
    const float* b_fc_proj = (const float*)d_in[8];
    const float* ln1_w     = (const float*)d_in[9];
    const float* ln1_b     = (const float*)d_in[10];
    const float* ln2_w     = (const float*)d_in[11];
    const float* ln2_b     = (const float*)d_in[12];
    float* outp            = (float*)d_out;

    float *px, *pqkv, *patt, *ph, *py, *pfc;
    cudaGetSymbolAddress((void**)&px,   g_x);
    cudaGetSymbolAddress((void**)&pqkv, g_qkv);
    cudaGetSymbolAddress((void**)&patt, g_att);
    cudaGetSymbolAddress((void**)&ph,   g_h);
    cudaGetSymbolAddress((void**)&py,   g_y);
    cudaGetSymbolAddress((void**)&pfc,  g_fc);

    // 1. LN1
    ln_kernel<<<MROWS, 256>>>(hidden, ln1_w, ln1_b, px);

    // 2. qkv = x @ w_attn + b_attn    [4096,1024]x[1024,3072]
    gemm_kernel<0><<<dim3(3 * DIM / 128, MROWS / 128), 256>>>(
        px, w_attn, b_attn, nullptr, pqkv, MROWS, 3 * DIM, DIM);

    // 3. causal flash attention -> g_att
    attn_kernel<<<dim3(SEQ / 64, BS_ * NH), 64>>>(pqkv, patt);

    // 4. h = hidden + attn @ w_proj + b_proj
    gemm_kernel<2><<<dim3(DIM / 128, MROWS / 128), 256>>>(
        patt, w_proj, b_proj, hidden, ph, MROWS, DIM, DIM);

    // 5. LN2
    ln_kernel<<<MROWS, 256>>>(ph, ln2_w, ln2_b, py);

    // 6. fc = gelu(y @ w_fc + b_fc)   [4096,1024]x[1024,4096]
    gemm_kernel<1><<<dim3(DFF / 128, MROWS / 128), 256>>>(
        py, w_fc, b_fc, nullptr, pfc, MROWS, DFF, DIM);

    // 7. out = h + fc @ w_fc_proj + b_fc_proj   [4096,4096]x[4096,1024]
    gemm_kernel<2><<<dim3(DIM / 128, MROWS / 128), 256>>>(
        pfc, w_fc_proj, b_fc_proj, ph, outp, MROWS, DIM, DFF);
}

// round 2
// speedup vs baseline: 2.9414x; 2.9414x over previous
#include <cuda_runtime.h>
#include <math.h>
#include <stdint.h>

#define BS_  2
#define SEQ  2048
#define DIM  1024
#define NH   16
#define DFF  4096
#define MROWS (BS_*SEQ)   // 4096

// ---------------- Scratch ------------------------------------------------------
__device__ float g_x  [MROWS * DIM];
__device__ float g_qkv[MROWS * 3 * DIM];
__device__ float g_att[MROWS * DIM];
__device__ float g_h  [MROWS * DIM];
__device__ float g_y  [MROWS * DIM];
__device__ float g_fc [MROWS * DFF];

// ---------------- helpers ------------------------------------------------------
__device__ __forceinline__ uint32_t f2tf(float f) {
    uint32_t u; asm("cvt.rna.tf32.f32 %0, %1;" : "=r"(u) : "f"(f)); return u;
}

__device__ __forceinline__ void mma8(float d[4], const uint32_t a[4], const uint32_t b[2]) {
    asm volatile("mma.sync.aligned.m16n8k8.row.col.f32.tf32.tf32.f32 "
        "{%0,%1,%2,%3}, {%4,%5,%6,%7}, {%8,%9}, {%0,%1,%2,%3};\n"
        : "+f"(d[0]), "+f"(d[1]), "+f"(d[2]), "+f"(d[3])
        : "r"(a[0]), "r"(a[1]), "r"(a[2]), "r"(a[3]), "r"(b[0]), "r"(b[1]));
}

__device__ __forceinline__ float gelu_f(float x) {
    float x3 = x * x * x;
    return 0.5f * x * (1.0f + tanhf(0.7978845608028654f * (x + 0.044715f * x3)));
}

// ---------------- LayerNorm ----------------------------------------------------
__global__ void __launch_bounds__(256)
ln_kernel(const float* __restrict__ in, const float* __restrict__ w,
          const float* __restrict__ b, float* __restrict__ out)
{
    int row = blockIdx.x;
    int t = threadIdx.x;
    const float4* ip = (const float4*)(in + (size_t)row * DIM);
    float4 x = ip[t];
    float s  = x.x + x.y + x.z + x.w;
    float ss = x.x*x.x + x.y*x.y + x.z*x.z + x.w*x.w;
    #pragma unroll
    for (int off = 16; off; off >>= 1) {
        s  += __shfl_xor_sync(0xFFFFFFFFu, s,  off);
        ss += __shfl_xor_sync(0xFFFFFFFFu, ss, off);
    }
    __shared__ float sh_s[8], sh_ss[8];
    int wid = t >> 5, lid = t & 31;
    if (lid == 0) { sh_s[wid] = s; sh_ss[wid] = ss; }
    __syncthreads();
    float S = 0.f, SS = 0.f;
    #pragma unroll
    for (int i = 0; i < 8; i++) { S += sh_s[i]; SS += sh_ss[i]; }
    float mean = S * (1.0f / DIM);
    float var  = SS * (1.0f / DIM) - mean * mean;
    float inv  = rsqrtf(var + 1e-6f);
    float4 wv = ((const float4*)w)[t];
    float4 bv = ((const float4*)b)[t];
    float4 r;
    r.x = (x.x - mean) * inv * wv.x + bv.x;
    r.y = (x.y - mean) * inv * wv.y + bv.y;
    r.z = (x.z - mean) * inv * wv.z + bv.z;
    r.w = (x.w - mean) * inv * wv.w + bv.w;
    ((float4*)(out + (size_t)row * DIM))[t] = r;
}

// ---------------- TF32 tensor-core GEMM ---------------------------------------
// C[M,N] = A[M,K] @ B[K,N] + bias (+epilogue). 128x128 tile, 256 threads,
// 8 warps (2x4), warp tile 64x32, mma m16n8k8 tf32, k-tile 32 double-buffered.
// SMEM: As m-major stride 36 (conflict-free), Bs k-major stride 136.
#define AS_BUF (128*36)
#define BS_BUF (32*136)
#define GEMM_SMEM ((2*AS_BUF + 2*BS_BUF) * 4)

template<int EPI>
__global__ void __launch_bounds__(256)
gemm_tf32(const float* __restrict__ A, const float* __restrict__ B,
          const float* __restrict__ bias, const float* __restrict__ res,
          float* __restrict__ C, int M, int N, int K)
{
    extern __shared__ uint32_t sm[];
    uint32_t* As = sm;                // 2 x 128 x 36
    uint32_t* Bs = sm + 2 * AS_BUF;   // 2 x 32 x 136

    const int t = threadIdx.x;
    const int lane = t & 31, w = t >> 5;
    const int wr = w >> 2, wc = w & 3;           // 2 x 4 warp grid
    const int g = lane >> 2, c = lane & 3;
    const int row0 = blockIdx.y * 128, col0 = blockIdx.x * 128;

    // producers
    const int am = t >> 1, ak = (t & 1) * 16;    // A: 128 rows x 2 half-k
    const float* Ap = A + (size_t)(row0 + am) * K + ak;
    uint32_t* AsW = As + am * 36 + ak;
    const int bk = t >> 3, bn = (t & 7) * 4;     // B: 32 rows x 8 lanes
    const float* Bp = B + (size_t)bk * N + col0 + bn;
    uint32_t* BsW = Bs + bk * 136 + bn;

    float acc[4][4][4];
    #pragma unroll
    for (int i = 0; i < 4; i++)
        #pragma unroll
        for (int j = 0; j < 4; j++)
            #pragma unroll
            for (int q = 0; q < 4; q++) acc[i][j][q] = 0.f;

    const int nk = K / 32;

    // prologue: tile 0
    {
        #pragma unroll
        for (int j = 0; j < 4; j++) {
            float4 v = *(const float4*)(Ap + 4 * j);
            *(uint4*)(AsW + 4 * j) = make_uint4(f2tf(v.x), f2tf(v.y), f2tf(v.z), f2tf(v.w));
        }
        #pragma unroll
        for (int j = 0; j < 4; j++) {
            float4 v = *(const float4*)(Bp + 32 * j);
            *(uint4*)(BsW + 32 * j) = make_uint4(f2tf(v.x), f2tf(v.y), f2tf(v.z), f2tf(v.w));
        }
    }
    __syncthreads();

    #pragma unroll 1
    for (int kt = 0; kt < nk; kt++) {
        const int cur = kt & 1;
        float4 na[4], nb[4];
        if (kt + 1 < nk) {
            #pragma unroll
            for (int j = 0; j < 4; j++)
                na[j] = *(const float4*)(Ap + (kt + 1) * 32 + 4 * j);
            #pragma unroll
            for (int j = 0; j < 4; j++)
                nb[j] = *(const float4*)(Bp + (size_t)(kt + 1) * 32 * N + 32 * j);
        }

        const uint32_t* Ab = As + cur * AS_BUF;
        const uint32_t* Bb = Bs + cur * BS_BUF;
        #pragma unroll
        for (int kk = 0; kk < 32; kk += 8) {
            uint32_t af[4][4], bf[4][2];
            #pragma unroll
            for (int mt = 0; mt < 4; mt++) {
                int base = (wr * 64 + mt * 16 + g) * 36 + kk + c;
                af[mt][0] = Ab[base];
                af[mt][2] = Ab[base + 4];
                af[mt][1] = Ab[base + 8 * 36];
                af[mt][3] = Ab[base + 8 * 36 + 4];
            }
            #pragma unroll
            for (int nt = 0; nt < 4; nt++) {
                int bidx = (kk + c) * 136 + wc * 32 + nt * 8 + g;
                bf[nt][0] = Bb[bidx];
                bf[nt][1] = Bb[bidx + 4 * 136];
            }
            #pragma unroll
            for (int mt = 0; mt < 4; mt++)
                #pragma unroll
                for (int nt = 0; nt < 4; nt++)
                    mma8(acc[mt][nt], af[mt], bf[nt]);
        }

        if (kt + 1 < nk) {
            uint32_t* Aw = AsW + (cur ^ 1) * AS_BUF;
            uint32_t* Bw = BsW + (cur ^ 1) * BS_BUF;
            #pragma unroll
            for (int j = 0; j < 4; j++)
                *(uint4*)(Aw + 4 * j) = make_uint4(f2tf(na[j].x), f2tf(na[j].y), f2tf(na[j].z), f2tf(na[j].w));
            #pragma unroll
            for (int j = 0; j < 4; j++)
                *(uint4*)(Bw + 32 * j) = make_uint4(f2tf(nb[j].x), f2tf(nb[j].y), f2tf(nb[j].z), f2tf(nb[j].w));
        }
        __syncthreads();
    }

    // epilogue
    #pragma unroll
    for (int mt = 0; mt < 4; mt++) {
        int r1 = row0 + wr * 64 + mt * 16 + g;
        int r2 = r1 + 8;
        #pragma unroll
        for (int nt = 0; nt < 4; nt++) {
            int col = col0 + wc * 32 + nt * 8 + 2 * c;
            float2 bv = *(const float2*)&bias[col];
            float v0 = acc[mt][nt][0] + bv.x;
            float v1 = acc[mt][nt][1] + bv.y;
            float v2 = acc[mt][nt][2] + bv.x;
            float v3 = acc[mt][nt][3] + bv.y;
            if (EPI == 1) {
                v0 = gelu_f(v0); v1 = gelu_f(v1); v2 = gelu_f(v2); v3 = gelu_f(v3);
            } else if (EPI == 2) {
                float2 ra = *(const float2*)&res[(size_t)r1 * N + col];
                float2 rb = *(const float2*)&res[(size_t)r2 * N + col];
                v0 += ra.x; v1 += ra.y; v2 += rb.x; v3 += rb.y;
            }
            *(float2*)&C[(size_t)r1 * N + col] = make_float2(v0, v1);
            *(float2*)&C[(size_t)r2 * N + col] = make_float2(v2, v3);
        }
    }
}

// ---------------- Flash attention with tf32 mma --------------------------------
// grid (SEQ/128, B*NH), 256 threads = 8 warps, warp owns 16 queries.
// K/V tiles of 64 in SMEM (tf32), online softmax on mma C fragments.
__global__ void __launch_bounds__(256)
attn_mma(const float* __restrict__ qkv, float* __restrict__ out)
{
    __shared__ uint32_t ks[64][68];
    __shared__ uint32_t vs[64][68];

    const int t = threadIdx.x, lane = t & 31, w = t >> 5;
    const int g = lane >> 2, c = lane & 3;
    const int bq = blockIdx.x * 128;
    const int b = blockIdx.y >> 4, h = blockIdx.y & 15;
    const int qg0 = bq + w * 16 + g;         // row for regs {0,1}; row+8 for {2,3}

    // Q fragments (held in registers for the whole kernel), pre-scaled
    uint32_t aq[8][4];
    {
        size_t q0 = ((size_t)(b * SEQ + qg0)) * (3 * DIM) + h * 64;
        size_t q1 = q0 + (size_t)8 * (3 * DIM);
        #pragma unroll
        for (int k8 = 0; k8 < 8; k8++) {
            aq[k8][0] = f2tf(qkv[q0 + k8 * 8 + c] * 0.125f);
            aq[k8][1] = f2tf(qkv[q1 + k8 * 8 + c] * 0.125f);
            aq[k8][2] = f2tf(qkv[q0 + k8 * 8 + c + 4] * 0.125f);
            aq[k8][3] = f2tf(qkv[q1 + k8 * 8 + c + 4] * 0.125f);
        }
    }

    float o[8][4];
    #pragma unroll
    for (int i = 0; i < 8; i++) { o[i][0] = o[i][1] = o[i][2] = o[i][3] = 0.f; }
    float m0 = -1e30f, m1 = -1e30f, l0 = 0.f, l1 = 0.f;

    const int r = t >> 2, d0 = (t & 3) * 16;   // K/V cooperative loader mapping
    const int kend = blockIdx.x * 2 + 1;

    #pragma unroll 1
    for (int kt = 0; kt <= kend; kt++) {
        // cooperative K/V tile load with tf32 conversion
        {
            const float* kp = qkv + ((size_t)(b * SEQ + kt * 64 + r)) * (3 * DIM) + DIM + h * 64 + d0;
            const float* vp = kp + DIM;
            #pragma unroll
            for (int jj = 0; jj < 4; jj++) {
                float4 kf = *(const float4*)(kp + 4 * jj);
                float4 vf = *(const float4*)(vp + 4 * jj);
                *(uint4*)&ks[r][d0 + 4 * jj] = make_uint4(f2tf(kf.x), f2tf(kf.y), f2tf(kf.z), f2tf(kf.w));
                *(uint4*)&vs[r][d0 + 4 * jj] = make_uint4(f2tf(vf.x), f2tf(vf.y), f2tf(vf.z), f2tf(vf.w));
            }
        }
        __syncthreads();

        // S = Q K^T for this warp's 16 queries x 64 keys
        float sacc[8][4];
        #pragma unroll
        for (int i = 0; i < 8; i++) { sacc[i][0] = sacc[i][1] = sacc[i][2] = sacc[i][3] = 0.f; }
        #pragma unroll
        for (int k8 = 0; k8 < 8; k8++) {
            uint32_t bb[8][2];
            #pragma unroll
            for (int nt = 0; nt < 8; nt++) {
                bb[nt][0] = ks[nt * 8 + g][k8 * 8 + c];
                bb[nt][1] = ks[nt * 8 + g][k8 * 8 + c + 4];
            }
            #pragma unroll
            for (int nt = 0; nt < 8; nt++)
                mma8(sacc[nt], aq[k8], bb[nt]);
        }

        // causal mask (only on diagonal-crossing tiles)
        if (kt * 64 + 63 > bq + w * 16) {
            #pragma unroll
            for (int nt = 0; nt < 8; nt++) {
                int colb = kt * 64 + nt * 8 + 2 * c;
                if (colb     > qg0)     sacc[nt][0] = -1e30f;
                if (colb + 1 > qg0)     sacc[nt][1] = -1e30f;
                if (colb     > qg0 + 8) sacc[nt][2] = -1e30f;
                if (colb + 1 > qg0 + 8) sacc[nt][3] = -1e30f;
            }
        }

        // online softmax
        float mx0 = -1e30f, mx1 = -1e30f;
        #pragma unroll
        for (int nt = 0; nt < 8; nt++) {
            mx0 = fmaxf(mx0, fmaxf(sacc[nt][0], sacc[nt][1]));
            mx1 = fmaxf(mx1, fmaxf(sacc[nt][2], sacc[nt][3]));
        }
        mx0 = fmaxf(mx0, __shfl_xor_sync(0xFFFFFFFFu, mx0, 1));
        mx0 = fmaxf(mx0, __shfl_xor_sync(0xFFFFFFFFu, mx0, 2));
        mx1 = fmaxf(mx1, __shfl_xor_sync(0xFFFFFFFFu, mx1, 1));
        mx1 = fmaxf(mx1, __shfl_xor_sync(0xFFFFFFFFu, mx1, 2));
        float nm0 = fmaxf(m0, mx0), nm1 = fmaxf(m1, mx1);
        float al0 = __expf(m0 - nm0), al1 = __expf(m1 - nm1);
        m0 = nm0; m1 = nm1;

        float ls0 = 0.f, ls1 = 0.f;
        uint32_t ps[8][4];
        #pragma unroll
        for (int nt = 0; nt < 8; nt++) {
            float p0 = __expf(sacc[nt][0] - nm0);
            float p1 = __expf(sacc[nt][1] - nm0);
            float p2 = __expf(sacc[nt][2] - nm1);
            float p3 = __expf(sacc[nt][3] - nm1);
            ls0 += p0 + p1; ls1 += p2 + p3;
            ps[nt][0] = f2tf(p0); ps[nt][1] = f2tf(p1);
            ps[nt][2] = f2tf(p2); ps[nt][3] = f2tf(p3);
            o[nt][0] *= al0; o[nt][1] *= al0;
            o[nt][2] *= al1; o[nt][3] *= al1;
        }
        ls0 += __shfl_xor_sync(0xFFFFFFFFu, ls0, 1);
        ls0 += __shfl_xor_sync(0xFFFFFFFFu, ls0, 2);
        ls1 += __shfl_xor_sync(0xFFFFFFFFu, ls1, 1);
        ls1 += __shfl_xor_sync(0xFFFFFFFFu, ls1, 2);
        l0 = l0 * al0 + ls0;
        l1 = l1 * al1 + ls1;

        // O += P V : re-fragment P via shuffles, mma against V tiles
        const int srcA = (lane & ~3) | (c >> 1);
        const int srcB = srcA + 2;
        #pragma unroll
        for (int kk = 0; kk < 8; kk++) {
            uint32_t s0a = __shfl_sync(0xFFFFFFFFu, ps[kk][0], srcA);
            uint32_t s1a = __shfl_sync(0xFFFFFFFFu, ps[kk][1], srcA);
            uint32_t s2a = __shfl_sync(0xFFFFFFFFu, ps[kk][2], srcA);
            uint32_t s3a = __shfl_sync(0xFFFFFFFFu, ps[kk][3], srcA);
            uint32_t s0b = __shfl_sync(0xFFFFFFFFu, ps[kk][0], srcB);
            uint32_t s1b = __shfl_sync(0xFFFFFFFFu, ps[kk][1], srcB);
            uint32_t s2b = __shfl_sync(0xFFFFFFFFu, ps[kk][2], srcB);
            uint32_t s3b = __shfl_sync(0xFFFFFFFFu, ps[kk][3], srcB);
            uint32_t pa[4];
            pa[0] = (c & 1) ? s1a : s0a;
            pa[1] = (c & 1) ? s3a : s2a;
            pa[2] = (c & 1) ? s1b : s0b;
            pa[3] = (c & 1) ? s3b : s2b;
            #pragma unroll
            for (int nt = 0; nt < 8; nt++) {
                uint32_t bv[2];
                bv[0] = vs[kk * 8 + c][nt * 8 + g];
                bv[1] = vs[kk * 8 + c + 4][nt * 8 + g];
                mma8(o[nt], pa, bv);
            }
        }
        __syncthreads();
    }

    // normalize + store
    float il0 = 1.0f / l0, il1 = 1.0f / l1;
    size_t o0 = ((size_t)(b * SEQ + qg0)) * DIM + h * 64;
    size_t o1 = o0 + (size_t)8 * DIM;
    #pragma unroll
    for (int nt = 0; nt < 8; nt++) {
        int cl = nt * 8 + 2 * c;
        *(float2*)&out[o0 + cl] = make_float2(o[nt][0] * il0, o[nt][1] * il0);
        *(float2*)&out[o1 + cl] = make_float2(o[nt][2] * il1, o[nt][3] * il1);
    }
}

// ---------------- Launch -------------------------------------------------------
extern "C" void kernel_launch(void* const* d_in, const int* in_sizes, int n_in,
                              void* d_out, int out_size)
{
    const float* hidden    = (const float*)d_in[0];
    const float* w_attn    = (const float*)d_in[1];
    const float* b_attn    = (const float*)d_in[2];
    const float* w_proj    = (const float*)d_in[3];
    const float* b_proj    = (const float*)d_in[4];
    const float* w_fc      = (const float*)d_in[5];
    const float* b_fc      = (const float*)d_in[6];
    const float* w_fc_proj = (const float*)d_in[7];
    const float* b_fc_proj = (const float*)d_in[8];
    const float* ln1_w     = (const float*)d_in[9];
    const float* ln1_b     = (const float*)d_in[10];
    const float* ln2_w     = (const float*)d_in[11];
    const float* ln2_b     = (const float*)d_in[12];
    float* outp            = (float*)d_out;

    float *px, *pqkv, *patt, *ph, *py, *pfc;
    cudaGetSymbolAddress((void**)&px,   g_x);
    cudaGetSymbolAddress((void**)&pqkv, g_qkv);
    cudaGetSymbolAddress((void**)&patt, g_att);
    cudaGetSymbolAddress((void**)&ph,   g_h);
    cudaGetSymbolAddress((void**)&py,   g_y);
    cudaGetSymbolAddress((void**)&pfc,  g_fc);

    cudaFuncSetAttribute(gemm_tf32<0>, cudaFuncAttributeMaxDynamicSharedMemorySize, GEMM_SMEM);
    cudaFuncSetAttribute(gemm_tf32<1>, cudaFuncAttributeMaxDynamicSharedMemorySize, GEMM_SMEM);
    cudaFuncSetAttribute(gemm_tf32<2>, cudaFuncAttributeMaxDynamicSharedMemorySize, GEMM_SMEM);

    // 1. LN1
    ln_kernel<<<MROWS, 256>>>(hidden, ln1_w, ln1_b, px);

    // 2. qkv = x @ w_attn + b_attn
    gemm_tf32<0><<<dim3(3 * DIM / 128, MROWS / 128), 256, GEMM_SMEM>>>(
        px, w_attn, b_attn, nullptr, pqkv, MROWS, 3 * DIM, DIM);

    // 3. causal flash attention
    attn_mma<<<dim3(SEQ / 128, BS_ * NH), 256>>>(pqkv, patt);

    // 4. h = hidden + attn @ w_proj + b_proj
    gemm_tf32<2><<<dim3(DIM / 128, MROWS / 128), 256, GEMM_SMEM>>>(
        patt, w_proj, b_proj, hidden, ph, MROWS, DIM, DIM);

    // 5. LN2
    ln_kernel<<<MROWS, 256>>>(ph, ln2_w, ln2_b, py);

    // 6. fc = gelu(y @ w_fc + b_fc)
    gemm_tf32<1><<<dim3(DFF / 128, MROWS / 128), 256, GEMM_SMEM>>>(
        py, w_fc, b_fc, nullptr, pfc, MROWS, DFF, DIM);

    // 7. out = h + fc @ w_fc_proj + b_fc_proj
    gemm_tf32<2><<<dim3(DIM / 128, MROWS / 128), 256, GEMM_SMEM>>>(
        pfc, w_fc_proj, b_fc_proj, ph, outp, MROWS, DIM, DFF);
}

// round 4
// speedup vs baseline: 4.0574x; 1.3794x over previous
#include <cuda_runtime.h>
#include <math.h>
#include <stdint.h>

#define BS_  2
#define SEQ  2048
#define DIM  1024
#define NH   16
#define DFF  4096
#define MROWS (BS_*SEQ)   // 4096

// ---------------- Scratch ------------------------------------------------------
__device__ float g_x  [MROWS * DIM];
__device__ float g_qkv[MROWS * 3 * DIM];
__device__ float g_att[MROWS * DIM];
__device__ float g_h  [MROWS * DIM];
__device__ float g_y  [MROWS * DIM];
__device__ float g_fc [MROWS * DFF];

// ---------------- helpers ------------------------------------------------------
__device__ __forceinline__ uint32_t f2tf(float f) {
    uint32_t u; asm("cvt.rna.tf32.f32 %0, %1;" : "=r"(u) : "f"(f)); return u;
}
__device__ __forceinline__ void mma8(float d[4], const uint32_t a[4], const uint32_t b[2]) {
    asm volatile("mma.sync.aligned.m16n8k8.row.col.f32.tf32.tf32.f32 "
        "{%0,%1,%2,%3}, {%4,%5,%6,%7}, {%8,%9}, {%0,%1,%2,%3};\n"
        : "+f"(d[0]), "+f"(d[1]), "+f"(d[2]), "+f"(d[3])
        : "r"(a[0]), "r"(a[1]), "r"(a[2]), "r"(a[3]), "r"(b[0]), "r"(b[1]));
}
__device__ __forceinline__ float gelu_f(float x) {
    float x3 = x * x * x;
    return 0.5f * x * (1.0f + tanhf(0.7978845608028654f * (x + 0.044715f * x3)));
}
__device__ __forceinline__ uint32_t smem_u32(const void* p) {
    uint32_t a;
    asm("{ .reg .u64 t; cvta.to.shared.u64 t, %1; cvt.u32.u64 %0, t; }" : "=r"(a) : "l"(p));
    return a;
}
__device__ __forceinline__ void cpa16(uint32_t dst, const float* src) {
    asm volatile("cp.async.cg.shared.global [%0], [%1], 16;" :: "r"(dst), "l"(src));
}

// ---------------- LayerNorm ----------------------------------------------------
__global__ void __launch_bounds__(256)
ln_kernel(const float* __restrict__ in, const float* __restrict__ w,
          const float* __restrict__ b, float* __restrict__ out)
{
    int row = blockIdx.x;
    int t = threadIdx.x;
    const float4* ip = (const float4*)(in + (size_t)row * DIM);
    float4 x = ip[t];
    float s  = x.x + x.y + x.z + x.w;
    float ss = x.x*x.x + x.y*x.y + x.z*x.z + x.w*x.w;
    #pragma unroll
    for (int off = 16; off; off >>= 1) {
        s  += __shfl_xor_sync(0xFFFFFFFFu, s,  off);
        ss += __shfl_xor_sync(0xFFFFFFFFu, ss, off);
    }
    __shared__ float sh_s[8], sh_ss[8];
    int wid = t >> 5, lid = t & 31;
    if (lid == 0) { sh_s[wid] = s; sh_ss[wid] = ss; }
    __syncthreads();
    float S = 0.f, SS = 0.f;
    #pragma unroll
    for (int i = 0; i < 8; i++) { S += sh_s[i]; SS += sh_ss[i]; }
    float mean = S * (1.0f / DIM);
    float var  = SS * (1.0f / DIM) - mean * mean;
    float inv  = rsqrtf(var + 1e-6f);
    float4 wv = ((const float4*)w)[t];
    float4 bv = ((const float4*)b)[t];
    float4 r;
    r.x = (x.x - mean) * inv * wv.x + bv.x;
    r.y = (x.y - mean) * inv * wv.y + bv.y;
    r.z = (x.z - mean) * inv * wv.z + bv.z;
    r.w = (x.w - mean) * inv * wv.w + bv.w;
    ((float4*)(out + (size_t)row * DIM))[t] = r;
}

// ---------------- TF32 mma.sync GEMM, cp.async 2-stage, 2 CTA/SM ---------------
// C[M,N] = A[M,K] @ B[K,N] + bias (+epilogue). 128x128 tile, 256 threads,
// 8 warps (2x4), warp tile 64x32, k-tile 32. fp32 in SMEM, tf32 cvt at frag load.
#define AS_STRIDE 36
#define BS_STRIDE 136
#define AS_FLOATS (128 * AS_STRIDE)             // 4608
#define BS_FLOATS (32 * BS_STRIDE)              // 4352
#define STG_FLOATS (AS_FLOATS + BS_FLOATS)      // 8960
#define GEMM_SMEM (2 * STG_FLOATS * 4)          // 71680 B

template<int EPI>
__global__ void __launch_bounds__(256, 2)
gemm_tf32(const float* __restrict__ A, const float* __restrict__ B,
          const float* __restrict__ bias, const float* __restrict__ res,
          float* __restrict__ C, int M, int N, int K)
{
    extern __shared__ float sm[];
    const uint32_t sb = smem_u32(sm);

    const int t = threadIdx.x;
    const int lane = t & 31, w = t >> 5;
    const int wr = w >> 2, wc = w & 3;
    const int g = lane >> 2, c = lane & 3;
    const int row0 = blockIdx.y * 128, col0 = blockIdx.x * 128;
    const int nk = K / 32;

    // producer mappings (4 x 16B chunks each for A and B per stage)
    uint32_t a_dst[4]; const float* a_src[4];
    #pragma unroll
    for (int j = 0; j < 4; j++) {
        int cid = t + 256 * j;
        int ar = cid >> 3, akc = (cid & 7) * 4;          // 128 rows x 8 chunks
        a_dst[j] = (ar * AS_STRIDE + akc) * 4;
        a_src[j] = A + (size_t)(row0 + ar) * K + akc;
    }
    uint32_t b_dst[4]; const float* b_src[4];
    #pragma unroll
    for (int j = 0; j < 4; j++) {
        int cid = t + 256 * j;
        int br = cid >> 5, bnc = (cid & 31) * 4;         // 32 rows x 32 chunks
        b_dst[j] = (br * BS_STRIDE + bnc) * 4;
        b_src[j] = B + (size_t)br * N + col0 + bnc;
    }

    float acc[4][4][4];
    #pragma unroll
    for (int i = 0; i < 4; i++)
        #pragma unroll
        for (int j = 0; j < 4; j++)
            #pragma unroll
            for (int q = 0; q < 4; q++) acc[i][j][q] = 0.f;

    // prologue: stages 0 and 1
    #pragma unroll
    for (int pt = 0; pt < 2; pt++) {
        uint32_t abase = sb + pt * STG_FLOATS * 4;
        uint32_t bbase = abase + AS_FLOATS * 4;
        #pragma unroll
        for (int j = 0; j < 4; j++) cpa16(abase + a_dst[j], a_src[j] + pt * 32);
        #pragma unroll
        for (int j = 0; j < 4; j++) cpa16(bbase + b_dst[j], b_src[j] + (size_t)pt * 32 * N);
        asm volatile("cp.async.commit_group;");
    }

    #pragma unroll 1
    for (int kt = 0; kt < nk; kt++) {
        asm volatile("cp.async.wait_group 1;");
        __syncthreads();

        const float* Ab = sm + (kt & 1) * STG_FLOATS;
        const float* Bb = Ab + AS_FLOATS;
        #pragma unroll
        for (int kk = 0; kk < 32; kk += 8) {
            uint32_t af[4][4], bf[4][2];
            #pragma unroll
            for (int mt = 0; mt < 4; mt++) {
                const float* ap = Ab + (wr * 64 + mt * 16 + g) * AS_STRIDE + kk + c;
                af[mt][0] = f2tf(ap[0]);
                af[mt][2] = f2tf(ap[4]);
                af[mt][1] = f2tf(ap[8 * AS_STRIDE]);
                af[mt][3] = f2tf(ap[8 * AS_STRIDE + 4]);
            }
            #pragma unroll
            for (int nt = 0; nt < 4; nt++) {
                const float* bp = Bb + (kk + c) * BS_STRIDE + wc * 32 + nt * 8 + g;
                bf[nt][0] = f2tf(bp[0]);
                bf[nt][1] = f2tf(bp[4 * BS_STRIDE]);
            }
            #pragma unroll
            for (int mt = 0; mt < 4; mt++)
                #pragma unroll
                for (int nt = 0; nt < 4; nt++)
                    mma8(acc[mt][nt], af[mt], bf[nt]);
        }
        __syncthreads();

        if (kt + 2 < nk) {
            uint32_t abase = sb + (kt & 1) * STG_FLOATS * 4;
            uint32_t bbase = abase + AS_FLOATS * 4;
            const int kkg = (kt + 2) * 32;
            #pragma unroll
            for (int j = 0; j < 4; j++) cpa16(abase + a_dst[j], a_src[j] + kkg);
            #pragma unroll
            for (int j = 0; j < 4; j++) cpa16(bbase + b_dst[j], b_src[j] + (size_t)kkg * N);
        }
        asm volatile("cp.async.commit_group;");
    }

    // epilogue
    #pragma unroll
    for (int mt = 0; mt < 4; mt++) {
        int r1 = row0 + wr * 64 + mt * 16 + g;
        int r2 = r1 + 8;
        #pragma unroll
        for (int nt = 0; nt < 4; nt++) {
            int col = col0 + wc * 32 + nt * 8 + 2 * c;
            float2 bv = *(const float2*)&bias[col];
            float v0 = acc[mt][nt][0] + bv.x;
            float v1 = acc[mt][nt][1] + bv.y;
            float v2 = acc[mt][nt][2] + bv.x;
            float v3 = acc[mt][nt][3] + bv.y;
            if (EPI == 1) {
                v0 = gelu_f(v0); v1 = gelu_f(v1); v2 = gelu_f(v2); v3 = gelu_f(v3);
            } else if (EPI == 2) {
                float2 ra = *(const float2*)&res[(size_t)r1 * N + col];
                float2 rb = *(const float2*)&res[(size_t)r2 * N + col];
                v0 += ra.x; v1 += ra.y; v2 += rb.x; v3 += rb.y;
            }
            *(float2*)&C[(size_t)r1 * N + col] = make_float2(v0, v1);
            *(float2*)&C[(size_t)r2 * N + col] = make_float2(v2, v3);
        }
    }
}

// ---------------- Flash attention with tf32 mma (round-2, unchanged) -----------
__global__ void __launch_bounds__(256)
attn_mma(const float* __restrict__ qkv, float* __restrict__ out)
{
    __shared__ uint32_t ks[64][68];
    __shared__ uint32_t vs[64][68];

    const int t = threadIdx.x, lane = t & 31, w = t >> 5;
    const int g = lane >> 2, c = lane & 3;
    const int bq = blockIdx.x * 128;
    const int b = blockIdx.y >> 4, h = blockIdx.y & 15;
    const int qg0 = bq + w * 16 + g;

    uint32_t aq[8][4];
    {
        size_t q0 = ((size_t)(b * SEQ + qg0)) * (3 * DIM) + h * 64;
        size_t q1 = q0 + (size_t)8 * (3 * DIM);
        #pragma unroll
        for (int k8 = 0; k8 < 8; k8++) {
            aq[k8][0] = f2tf(qkv[q0 + k8 * 8 + c] * 0.125f);
            aq[k8][1] = f2tf(qkv[q1 + k8 * 8 + c] * 0.125f);
            aq[k8][2] = f2tf(qkv[q0 + k8 * 8 + c + 4] * 0.125f);
            aq[k8][3] = f2tf(qkv[q1 + k8 * 8 + c + 4] * 0.125f);
        }
    }

    float o[8][4];
    #pragma unroll
    for (int i = 0; i < 8; i++) { o[i][0] = o[i][1] = o[i][2] = o[i][3] = 0.f; }
    float m0 = -1e30f, m1 = -1e30f, l0 = 0.f, l1 = 0.f;

    const int r = t >> 2, d0 = (t & 3) * 16;
    const int kend = blockIdx.x * 2 + 1;

    #pragma unroll 1
    for (int kt = 0; kt <= kend; kt++) {
        {
            const float* kp = qkv + ((size_t)(b * SEQ + kt * 64 + r)) * (3 * DIM) + DIM + h * 64 + d0;
            const float* vp = kp + DIM;
            #pragma unroll
            for (int jj = 0; jj < 4; jj++) {
                float4 kf = *(const float4*)(kp + 4 * jj);
                float4 vf = *(const float4*)(vp + 4 * jj);
                *(uint4*)&ks[r][d0 + 4 * jj] = make_uint4(f2tf(kf.x), f2tf(kf.y), f2tf(kf.z), f2tf(kf.w));
                *(uint4*)&vs[r][d0 + 4 * jj] = make_uint4(f2tf(vf.x), f2tf(vf.y), f2tf(vf.z), f2tf(vf.w));
            }
        }
        __syncthreads();

        float sacc[8][4];
        #pragma unroll
        for (int i = 0; i < 8; i++) { sacc[i][0] = sacc[i][1] = sacc[i][2] = sacc[i][3] = 0.f; }
        #pragma unroll
        for (int k8 = 0; k8 < 8; k8++) {
            uint32_t bb[8][2];
            #pragma unroll
            for (int nt = 0; nt < 8; nt++) {
                bb[nt][0] = ks[nt * 8 + g][k8 * 8 + c];
                bb[nt][1] = ks[nt * 8 + g][k8 * 8 + c + 4];
            }
            #pragma unroll
            for (int nt = 0; nt < 8; nt++)
                mma8(sacc[nt], aq[k8], bb[nt]);
        }

        if (kt * 64 + 63 > bq + w * 16) {
            #pragma unroll
            for (int nt = 0; nt < 8; nt++) {
                int colb = kt * 64 + nt * 8 + 2 * c;
                if (colb     > qg0)     sacc[nt][0] = -1e30f;
                if (colb + 1 > qg0)     sacc[nt][1] = -1e30f;
                if (colb     > qg0 + 8) sacc[nt][2] = -1e30f;
                if (colb + 1 > qg0 + 8) sacc[nt][3] = -1e30f;
            }
        }

        float mx0 = -1e30f, mx1 = -1e30f;
        #pragma unroll
        for (int nt = 0; nt < 8; nt++) {
            mx0 = fmaxf(mx0, fmaxf(sacc[nt][0], sacc[nt][1]));
            mx1 = fmaxf(mx1, fmaxf(sacc[nt][2], sacc[nt][3]));
        }
        mx0 = fmaxf(mx0, __shfl_xor_sync(0xFFFFFFFFu, mx0, 1));
        mx0 = fmaxf(mx0, __shfl_xor_sync(0xFFFFFFFFu, mx0, 2));
        mx1 = fmaxf(mx1, __shfl_xor_sync(0xFFFFFFFFu, mx1, 1));
        mx1 = fmaxf(mx1, __shfl_xor_sync(0xFFFFFFFFu, mx1, 2));
        float nm0 = fmaxf(m0, mx0), nm1 = fmaxf(m1, mx1);
        float al0 = __expf(m0 - nm0), al1 = __expf(m1 - nm1);
        m0 = nm0; m1 = nm1;

        float ls0 = 0.f, ls1 = 0.f;
        uint32_t ps[8][4];
        #pragma unroll
        for (int nt = 0; nt < 8; nt++) {
            float p0 = __expf(sacc[nt][0] - nm0);
            float p1 = __expf(sacc[nt][1] - nm0);
            float p2 = __expf(sacc[nt][2] - nm1);
            float p3 = __expf(sacc[nt][3] - nm1);
            ls0 += p0 + p1; ls1 += p2 + p3;
            ps[nt][0] = f2tf(p0); ps[nt][1] = f2tf(p1);
            ps[nt][2] = f2tf(p2); ps[nt][3] = f2tf(p3);
            o[nt][0] *= al0; o[nt][1] *= al0;
            o[nt][2] *= al1; o[nt][3] *= al1;
        }
        ls0 += __shfl_xor_sync(0xFFFFFFFFu, ls0, 1);
        ls0 += __shfl_xor_sync(0xFFFFFFFFu, ls0, 2);
        ls1 += __shfl_xor_sync(0xFFFFFFFFu, ls1, 1);
        ls1 += __shfl_xor_sync(0xFFFFFFFFu, ls1, 2);
        l0 = l0 * al0 + ls0;
        l1 = l1 * al1 + ls1;

        const int srcA = (lane & ~3) | (c >> 1);
        const int srcB = srcA + 2;
        #pragma unroll
        for (int kk = 0; kk < 8; kk++) {
            uint32_t s0a = __shfl_sync(0xFFFFFFFFu, ps[kk][0], srcA);
            uint32_t s1a = __shfl_sync(0xFFFFFFFFu, ps[kk][1], srcA);
            uint32_t s2a = __shfl_sync(0xFFFFFFFFu, ps[kk][2], srcA);
            uint32_t s3a = __shfl_sync(0xFFFFFFFFu, ps[kk][3], srcA);
            uint32_t s0b = __shfl_sync(0xFFFFFFFFu, ps[kk][0], srcB);
            uint32_t s1b = __shfl_sync(0xFFFFFFFFu, ps[kk][1], srcB);
            uint32_t s2b = __shfl_sync(0xFFFFFFFFu, ps[kk][2], srcB);
            uint32_t s3b = __shfl_sync(0xFFFFFFFFu, ps[kk][3], srcB);
            uint32_t pa[4];
            pa[0] = (c & 1) ? s1a : s0a;
            pa[1] = (c & 1) ? s3a : s2a;
            pa[2] = (c & 1) ? s1b : s0b;
            pa[3] = (c & 1) ? s3b : s2b;
            #pragma unroll
            for (int nt = 0; nt < 8; nt++) {
                uint32_t bv[2];
                bv[0] = vs[kk * 8 + c][nt * 8 + g];
                bv[1] = vs[kk * 8 + c + 4][nt * 8 + g];
                mma8(o[nt], pa, bv);
            }
        }
        __syncthreads();
    }

    float il0 = 1.0f / l0, il1 = 1.0f / l1;
    size_t o0 = ((size_t)(b * SEQ + qg0)) * DIM + h * 64;
    size_t o1 = o0 + (size_t)8 * DIM;
    #pragma unroll
    for (int nt = 0; nt < 8; nt++) {
        int cl = nt * 8 + 2 * c;
        *(float2*)&out[o0 + cl] = make_float2(o[nt][0] * il0, o[nt][1] * il0);
        *(float2*)&out[o1 + cl] = make_float2(o[nt][2] * il1, o[nt][3] * il1);
    }
}

// ---------------- Launch -------------------------------------------------------
extern "C" void kernel_launch(void* const* d_in, const int* in_sizes, int n_in,
                              void* d_out, int out_size)
{
    const float* hidden    = (const float*)d_in[0];
    const float* w_attn    = (const float*)d_in[1];
    const float* b_attn    = (const float*)d_in[2];
    const float* w_proj    = (const float*)d_in[3];
    const float* b_proj    = (const float*)d_in[4];
    const float* w_fc      = (const float*)d_in[5];
    const float* b_fc      = (const float*)d_in[6];
    const float* w_fc_proj = (const float*)d_in[7];
    const float* b_fc_proj = (const float*)d_in[8];
    const float* ln1_w     = (const float*)d_in[9];
    const float* ln1_b     = (const float*)d_in[10];
    const float* ln2_w     = (const float*)d_in[11];
    const float* ln2_b     = (const float*)d_in[12];
    float* outp            = (float*)d_out;

    float *px, *pqkv, *patt, *ph, *py, *pfc;
    cudaGetSymbolAddress((void**)&px,   g_x);
    cudaGetSymbolAddress((void**)&pqkv, g_qkv);
    cudaGetSymbolAddress((void**)&patt, g_att);
    cudaGetSymbolAddress((void**)&ph,   g_h);
    cudaGetSymbolAddress((void**)&py,   g_y);
    cudaGetSymbolAddress((void**)&pfc,  g_fc);

    cudaFuncSetAttribute(gemm_tf32<0>, cudaFuncAttributeMaxDynamicSharedMemorySize, GEMM_SMEM);
    cudaFuncSetAttribute(gemm_tf32<1>, cudaFuncAttributeMaxDynamicSharedMemorySize, GEMM_SMEM);
    cudaFuncSetAttribute(gemm_tf32<2>, cudaFuncAttributeMaxDynamicSharedMemorySize, GEMM_SMEM);

    // 1. LN1
    ln_kernel<<<MROWS, 256>>>(hidden, ln1_w, ln1_b, px);

    // 2. qkv = x @ w_attn + b_attn
    gemm_tf32<0><<<dim3(3 * DIM / 128, MROWS / 128), 256, GEMM_SMEM>>>(
        px, w_attn, b_attn, nullptr, pqkv, MROWS, 3 * DIM, DIM);

    // 3. causal flash attention
    attn_mma<<<dim3(SEQ / 128, BS_ * NH), 256>>>(pqkv, patt);

    // 4. h = hidden + attn @ w_proj + b_proj
    gemm_tf32<2><<<dim3(DIM / 128, MROWS / 128), 256, GEMM_SMEM>>>(
        patt, w_proj, b_proj, hidden, ph, MROWS, DIM, DIM);

    // 5. LN2
    ln_kernel<<<MROWS, 256>>>(ph, ln2_w, ln2_b, py);

    // 6. fc = gelu(y @ w_fc + b_fc)
    gemm_tf32<1><<<dim3(DFF / 128, MROWS / 128), 256, GEMM_SMEM>>>(
        py, w_fc, b_fc, nullptr, pfc, MROWS, DFF, DIM);

    // 7. out = h + fc @ w_fc_proj + b_fc_proj
    gemm_tf32<2><<<dim3(DIM / 128, MROWS / 128), 256, GEMM_SMEM>>>(
        pfc, w_fc_proj, b_fc_proj, ph, outp, MROWS, DIM, DFF);
}

// round 5
// speedup vs baseline: 4.1643x; 1.0263x over previous
#include <cuda_runtime.h>
#include <math.h>
#include <stdint.h>

#define BS_  2
#define SEQ  2048
#define DIM  1024
#define NH   16
#define DFF  4096
#define MROWS (BS_*SEQ)   // 4096

// ---------------- Scratch ------------------------------------------------------
__device__ float g_x  [MROWS * DIM];
__device__ float g_qkv[MROWS * 3 * DIM];
__device__ float g_att[MROWS * DIM];
__device__ float g_h  [MROWS * DIM];
__device__ float g_y  [MROWS * DIM];
__device__ float g_fc [MROWS * DFF];

// ---------------- helpers ------------------------------------------------------
// NOTE: tf32 mma reads fp32-aligned registers and ignores the low 13 mantissa
// bits, so raw fp32 bits are valid tf32 operands (truncation instead of RNA).
__device__ __forceinline__ void mma8(float d[4], const uint32_t a[4], const uint32_t b[2]) {
    asm volatile("mma.sync.aligned.m16n8k8.row.col.f32.tf32.tf32.f32 "
        "{%0,%1,%2,%3}, {%4,%5,%6,%7}, {%8,%9}, {%0,%1,%2,%3};\n"
        : "+f"(d[0]), "+f"(d[1]), "+f"(d[2]), "+f"(d[3])
        : "r"(a[0]), "r"(a[1]), "r"(a[2]), "r"(a[3]), "r"(b[0]), "r"(b[1]));
}
__device__ __forceinline__ float gelu_f(float x) {
    float x3 = x * x * x;
    return 0.5f * x * (1.0f + tanhf(0.7978845608028654f * (x + 0.044715f * x3)));
}
__device__ __forceinline__ uint32_t smem_u32(const void* p) {
    uint32_t a;
    asm("{ .reg .u64 t; cvta.to.shared.u64 t, %1; cvt.u32.u64 %0, t; }" : "=r"(a) : "l"(p));
    return a;
}
__device__ __forceinline__ void cpa16(uint32_t dst, const float* src) {
    asm volatile("cp.async.cg.shared.global [%0], [%1], 16;" :: "r"(dst), "l"(src));
}

// ---------------- LayerNorm ----------------------------------------------------
__global__ void __launch_bounds__(256)
ln_kernel(const float* __restrict__ in, const float* __restrict__ w,
          const float* __restrict__ b, float* __restrict__ out)
{
    int row = blockIdx.x;
    int t = threadIdx.x;
    const float4* ip = (const float4*)(in + (size_t)row * DIM);
    float4 x = ip[t];
    float s  = x.x + x.y + x.z + x.w;
    float ss = x.x*x.x + x.y*x.y + x.z*x.z + x.w*x.w;
    #pragma unroll
    for (int off = 16; off; off >>= 1) {
        s  += __shfl_xor_sync(0xFFFFFFFFu, s,  off);
        ss += __shfl_xor_sync(0xFFFFFFFFu, ss, off);
    }
    __shared__ float sh_s[8], sh_ss[8];
    int wid = t >> 5, lid = t & 31;
    if (lid == 0) { sh_s[wid] = s; sh_ss[wid] = ss; }
    __syncthreads();
    float S = 0.f, SS = 0.f;
    #pragma unroll
    for (int i = 0; i < 8; i++) { S += sh_s[i]; SS += sh_ss[i]; }
    float mean = S * (1.0f / DIM);
    float var  = SS * (1.0f / DIM) - mean * mean;
    float inv  = rsqrtf(var + 1e-6f);
    float4 wv = ((const float4*)w)[t];
    float4 bv = ((const float4*)b)[t];
    float4 r;
    r.x = (x.x - mean) * inv * wv.x + bv.x;
    r.y = (x.y - mean) * inv * wv.y + bv.y;
    r.z = (x.z - mean) * inv * wv.z + bv.z;
    r.w = (x.w - mean) * inv * wv.w + bv.w;
    ((float4*)(out + (size_t)row * DIM))[t] = r;
}

// ---------------- TF32 mma.sync GEMM, cp.async 2-stage, 2 CTA/SM ---------------
#define AS_STRIDE 36
#define BS_STRIDE 136
#define AS_FLOATS (128 * AS_STRIDE)
#define BS_FLOATS (32 * BS_STRIDE)
#define STG_FLOATS (AS_FLOATS + BS_FLOATS)
#define GEMM_SMEM (2 * STG_FLOATS * 4)

template<int EPI>
__global__ void __launch_bounds__(256, 2)
gemm_tf32(const float* __restrict__ A, const float* __restrict__ B,
          const float* __restrict__ bias, const float* __restrict__ res,
          float* __restrict__ C, int M, int N, int K)
{
    extern __shared__ float sm[];
    const uint32_t sb = smem_u32(sm);
    const uint32_t* smu = (const uint32_t*)sm;

    const int t = threadIdx.x;
    const int lane = t & 31, w = t >> 5;
    const int wr = w >> 2, wc = w & 3;
    const int g = lane >> 2, c = lane & 3;
    const int row0 = blockIdx.y * 128, col0 = blockIdx.x * 128;
    const int nk = K / 32;

    uint32_t a_dst[4]; const float* a_src[4];
    #pragma unroll
    for (int j = 0; j < 4; j++) {
        int cid = t + 256 * j;
        int ar = cid >> 3, akc = (cid & 7) * 4;
        a_dst[j] = (ar * AS_STRIDE + akc) * 4;
        a_src[j] = A + (size_t)(row0 + ar) * K + akc;
    }
    uint32_t b_dst[4]; const float* b_src[4];
    #pragma unroll
    for (int j = 0; j < 4; j++) {
        int cid = t + 256 * j;
        int br = cid >> 5, bnc = (cid & 31) * 4;
        b_dst[j] = (br * BS_STRIDE + bnc) * 4;
        b_src[j] = B + (size_t)br * N + col0 + bnc;
    }

    float acc[4][4][4];
    #pragma unroll
    for (int i = 0; i < 4; i++)
        #pragma unroll
        for (int j = 0; j < 4; j++)
            #pragma unroll
            for (int q = 0; q < 4; q++) acc[i][j][q] = 0.f;

    #pragma unroll
    for (int pt = 0; pt < 2; pt++) {
        uint32_t abase = sb + pt * STG_FLOATS * 4;
        uint32_t bbase = abase + AS_FLOATS * 4;
        #pragma unroll
        for (int j = 0; j < 4; j++) cpa16(abase + a_dst[j], a_src[j] + pt * 32);
        #pragma unroll
        for (int j = 0; j < 4; j++) cpa16(bbase + b_dst[j], b_src[j] + (size_t)pt * 32 * N);
        asm volatile("cp.async.commit_group;");
    }

    #pragma unroll 1
    for (int kt = 0; kt < nk; kt++) {
        asm volatile("cp.async.wait_group 1;");
        __syncthreads();

        const uint32_t* Ab = smu + (kt & 1) * STG_FLOATS;
        const uint32_t* Bb = Ab + AS_FLOATS;
        #pragma unroll
        for (int kk = 0; kk < 32; kk += 8) {
            uint32_t af[4][4], bf[4][2];
            #pragma unroll
            for (int mt = 0; mt < 4; mt++) {
                const uint32_t* ap = Ab + (wr * 64 + mt * 16 + g) * AS_STRIDE + kk + c;
                af[mt][0] = ap[0];
                af[mt][2] = ap[4];
                af[mt][1] = ap[8 * AS_STRIDE];
                af[mt][3] = ap[8 * AS_STRIDE + 4];
            }
            #pragma unroll
            for (int nt = 0; nt < 4; nt++) {
                const uint32_t* bp = Bb + (kk + c) * BS_STRIDE + wc * 32 + nt * 8 + g;
                bf[nt][0] = bp[0];
                bf[nt][1] = bp[4 * BS_STRIDE];
            }
            #pragma unroll
            for (int mt = 0; mt < 4; mt++)
                #pragma unroll
                for (int nt = 0; nt < 4; nt++)
                    mma8(acc[mt][nt], af[mt], bf[nt]);
        }
        __syncthreads();

        if (kt + 2 < nk) {
            uint32_t abase = sb + (kt & 1) * STG_FLOATS * 4;
            uint32_t bbase = abase + AS_FLOATS * 4;
            const int kkg = (kt + 2) * 32;
            #pragma unroll
            for (int j = 0; j < 4; j++) cpa16(abase + a_dst[j], a_src[j] + kkg);
            #pragma unroll
            for (int j = 0; j < 4; j++) cpa16(bbase + b_dst[j], b_src[j] + (size_t)kkg * N);
        }
        asm volatile("cp.async.commit_group;");
    }

    #pragma unroll
    for (int mt = 0; mt < 4; mt++) {
        int r1 = row0 + wr * 64 + mt * 16 + g;
        int r2 = r1 + 8;
        #pragma unroll
        for (int nt = 0; nt < 4; nt++) {
            int col = col0 + wc * 32 + nt * 8 + 2 * c;
            float2 bv = *(const float2*)&bias[col];
            float v0 = acc[mt][nt][0] + bv.x;
            float v1 = acc[mt][nt][1] + bv.y;
            float v2 = acc[mt][nt][2] + bv.x;
            float v3 = acc[mt][nt][3] + bv.y;
            if (EPI == 1) {
                v0 = gelu_f(v0); v1 = gelu_f(v1); v2 = gelu_f(v2); v3 = gelu_f(v3);
            } else if (EPI == 2) {
                float2 ra = *(const float2*)&res[(size_t)r1 * N + col];
                float2 rb = *(const float2*)&res[(size_t)r2 * N + col];
                v0 += ra.x; v1 += ra.y; v2 += rb.x; v3 += rb.y;
            }
            *(float2*)&C[(size_t)r1 * N + col] = make_float2(v0, v1);
            *(float2*)&C[(size_t)r2 * N + col] = make_float2(v2, v3);
        }
    }
}

// ---------------- Flash attention with tf32 mma (raw fp32 operands) ------------
__global__ void __launch_bounds__(256)
attn_mma(const float* __restrict__ qkv, float* __restrict__ out)
{
    __shared__ uint32_t ks[64][68];
    __shared__ uint32_t vs[64][68];

    const int t = threadIdx.x, lane = t & 31, w = t >> 5;
    const int g = lane >> 2, c = lane & 3;
    const int bq = blockIdx.x * 128;
    const int b = blockIdx.y >> 4, h = blockIdx.y & 15;
    const int qg0 = bq + w * 16 + g;

    uint32_t aq[8][4];
    {
        size_t q0 = ((size_t)(b * SEQ + qg0)) * (3 * DIM) + h * 64;
        size_t q1 = q0 + (size_t)8 * (3 * DIM);
        #pragma unroll
        for (int k8 = 0; k8 < 8; k8++) {
            aq[k8][0] = __float_as_uint(qkv[q0 + k8 * 8 + c] * 0.125f);
            aq[k8][1] = __float_as_uint(qkv[q1 + k8 * 8 + c] * 0.125f);
            aq[k8][2] = __float_as_uint(qkv[q0 + k8 * 8 + c + 4] * 0.125f);
            aq[k8][3] = __float_as_uint(qkv[q1 + k8 * 8 + c + 4] * 0.125f);
        }
    }

    float o[8][4];
    #pragma unroll
    for (int i = 0; i < 8; i++) { o[i][0] = o[i][1] = o[i][2] = o[i][3] = 0.f; }
    float m0 = -1e30f, m1 = -1e30f, l0 = 0.f, l1 = 0.f;

    const int r = t >> 2, d0 = (t & 3) * 16;
    const int kend = blockIdx.x * 2 + 1;

    #pragma unroll 1
    for (int kt = 0; kt <= kend; kt++) {
        {
            const float* kp = qkv + ((size_t)(b * SEQ + kt * 64 + r)) * (3 * DIM) + DIM + h * 64 + d0;
            const float* vp = kp + DIM;
            #pragma unroll
            for (int jj = 0; jj < 4; jj++) {
                *(float4*)&ks[r][d0 + 4 * jj] = *(const float4*)(kp + 4 * jj);
                *(float4*)&vs[r][d0 + 4 * jj] = *(const float4*)(vp + 4 * jj);
            }
        }
        __syncthreads();

        float sacc[8][4];
        #pragma unroll
        for (int i = 0; i < 8; i++) { sacc[i][0] = sacc[i][1] = sacc[i][2] = sacc[i][3] = 0.f; }
        #pragma unroll
        for (int k8 = 0; k8 < 8; k8++) {
            uint32_t bb[8][2];
            #pragma unroll
            for (int nt = 0; nt < 8; nt++) {
                bb[nt][0] = ks[nt * 8 + g][k8 * 8 + c];
                bb[nt][1] = ks[nt * 8 + g][k8 * 8 + c + 4];
            }
            #pragma unroll
            for (int nt = 0; nt < 8; nt++)
                mma8(sacc[nt], aq[k8], bb[nt]);
        }

        if (kt * 64 + 63 > bq + w * 16) {
            #pragma unroll
            for (int nt = 0; nt < 8; nt++) {
                int colb = kt * 64 + nt * 8 + 2 * c;
                if (colb     > qg0)     sacc[nt][0] = -1e30f;
                if (colb + 1 > qg0)     sacc[nt][1] = -1e30f;
                if (colb     > qg0 + 8) sacc[nt][2] = -1e30f;
                if (colb + 1 > qg0 + 8) sacc[nt][3] = -1e30f;
            }
        }

        float mx0 = -1e30f, mx1 = -1e30f;
        #pragma unroll
        for (int nt = 0; nt < 8; nt++) {
            mx0 = fmaxf(mx0, fmaxf(sacc[nt][0], sacc[nt][1]));
            mx1 = fmaxf(mx1, fmaxf(sacc[nt][2], sacc[nt][3]));
        }
        mx0 = fmaxf(mx0, __shfl_xor_sync(0xFFFFFFFFu, mx0, 1));
        mx0 = fmaxf(mx0, __shfl_xor_sync(0xFFFFFFFFu, mx0, 2));
        mx1 = fmaxf(mx1, __shfl_xor_sync(0xFFFFFFFFu, mx1, 1));
        mx1 = fmaxf(mx1, __shfl_xor_sync(0xFFFFFFFFu, mx1, 2));
        float nm0 = fmaxf(m0, mx0), nm1 = fmaxf(m1, mx1);
        float al0 = __expf(m0 - nm0), al1 = __expf(m1 - nm1);
        m0 = nm0; m1 = nm1;

        float ls0 = 0.f, ls1 = 0.f;
        uint32_t ps[8][4];
        #pragma unroll
        for (int nt = 0; nt < 8; nt++) {
            float p0 = __expf(sacc[nt][0] - nm0);
            float p1 = __expf(sacc[nt][1] - nm0);
            float p2 = __expf(sacc[nt][2] - nm1);
            float p3 = __expf(sacc[nt][3] - nm1);
            ls0 += p0 + p1; ls1 += p2 + p3;
            ps[nt][0] = __float_as_uint(p0); ps[nt][1] = __float_as_uint(p1);
            ps[nt][2] = __float_as_uint(p2); ps[nt][3] = __float_as_uint(p3);
            o[nt][0] *= al0; o[nt][1] *= al0;
            o[nt][2] *= al1; o[nt][3] *= al1;
        }
        ls0 += __shfl_xor_sync(0xFFFFFFFFu, ls0, 1);
        ls0 += __shfl_xor_sync(0xFFFFFFFFu, ls0, 2);
        ls1 += __shfl_xor_sync(0xFFFFFFFFu, ls1, 1);
        ls1 += __shfl_xor_sync(0xFFFFFFFFu, ls1, 2);
        l0 = l0 * al0 + ls0;
        l1 = l1 * al1 + ls1;

        const int srcA = (lane & ~3) | (c >> 1);
        const int srcB = srcA + 2;
        #pragma unroll
        for (int kk = 0; kk < 8; kk++) {
            uint32_t s0a = __shfl_sync(0xFFFFFFFFu, ps[kk][0], srcA);
            uint32_t s1a = __shfl_sync(0xFFFFFFFFu, ps[kk][1], srcA);
            uint32_t s2a = __shfl_sync(0xFFFFFFFFu, ps[kk][2], srcA);
            uint32_t s3a = __shfl_sync(0xFFFFFFFFu, ps[kk][3], srcA);
            uint32_t s0b = __shfl_sync(0xFFFFFFFFu, ps[kk][0], srcB);
            uint32_t s1b = __shfl_sync(0xFFFFFFFFu, ps[kk][1], srcB);
            uint32_t s2b = __shfl_sync(0xFFFFFFFFu, ps[kk][2], srcB);
            uint32_t s3b = __shfl_sync(0xFFFFFFFFu, ps[kk][3], srcB);
            uint32_t pa[4];
            pa[0] = (c & 1) ? s1a : s0a;
            pa[1] = (c & 1) ? s3a : s2a;
            pa[2] = (c & 1) ? s1b : s0b;
            pa[3] = (c & 1) ? s3b : s2b;
            #pragma unroll
            for (int nt = 0; nt < 8; nt++) {
                uint32_t bv[2];
                bv[0] = vs[kk * 8 + c][nt * 8 + g];
                bv[1] = vs[kk * 8 + c + 4][nt * 8 + g];
                mma8(o[nt], pa, bv);
            }
        }
        __syncthreads();
    }

    float il0 = 1.0f / l0, il1 = 1.0f / l1;
    size_t o0 = ((size_t)(b * SEQ + qg0)) * DIM + h * 64;
    size_t o1 = o0 + (size_t)8 * DIM;
    #pragma unroll
    for (int nt = 0; nt < 8; nt++) {
        int cl = nt * 8 + 2 * c;
        *(float2*)&out[o0 + cl] = make_float2(o[nt][0] * il0, o[nt][1] * il0);
        *(float2*)&out[o1 + cl] = make_float2(o[nt][2] * il1, o[nt][3] * il1);
    }
}

// ---------------- Launch -------------------------------------------------------
extern "C" void kernel_launch(void* const* d_in, const int* in_sizes, int n_in,
                              void* d_out, int out_size)
{
    const float* hidden    = (const float*)d_in[0];
    const float* w_attn    = (const float*)d_in[1];
    const float* b_attn    = (const float*)d_in[2];
    const float* w_proj    = (const float*)d_in[3];
    const float* b_proj    = (const float*)d_in[4];
    const float* w_fc      = (const float*)d_in[5];
    const float* b_fc      = (const float*)d_in[6];
    const float* w_fc_proj = (const float*)d_in[7];
    const float* b_fc_proj = (const float*)d_in[8];
    const float* ln1_w     = (const float*)d_in[9];
    const float* ln1_b     = (const float*)d_in[10];
    const float* ln2_w     = (const float*)d_in[11];
    const float* ln2_b     = (const float*)d_in[12];
    float* outp            = (float*)d_out;

    float *px, *pqkv, *patt, *ph, *py, *pfc;
    cudaGetSymbolAddress((void**)&px,   g_x);
    cudaGetSymbolAddress((void**)&pqkv, g_qkv);
    cudaGetSymbolAddress((void**)&patt, g_att);
    cudaGetSymbolAddress((void**)&ph,   g_h);
    cudaGetSymbolAddress((void**)&py,   g_y);
    cudaGetSymbolAddress((void**)&pfc,  g_fc);

    cudaFuncSetAttribute(gemm_tf32<0>, cudaFuncAttributeMaxDynamicSharedMemorySize, GEMM_SMEM);
    cudaFuncSetAttribute(gemm_tf32<1>, cudaFuncAttributeMaxDynamicSharedMemorySize, GEMM_SMEM);
    cudaFuncSetAttribute(gemm_tf32<2>, cudaFuncAttributeMaxDynamicSharedMemorySize, GEMM_SMEM);

    ln_kernel<<<MROWS, 256>>>(hidden, ln1_w, ln1_b, px);

    gemm_tf32<0><<<dim3(3 * DIM / 128, MROWS / 128), 256, GEMM_SMEM>>>(
        px, w_attn, b_attn, nullptr, pqkv, MROWS, 3 * DIM, DIM);

    attn_mma<<<dim3(SEQ / 128, BS_ * NH), 256>>>(pqkv, patt);

    gemm_tf32<2><<<dim3(DIM / 128, MROWS / 128), 256, GEMM_SMEM>>>(
        patt, w_proj, b_proj, hidden, ph, MROWS, DIM, DIM);

    ln_kernel<<<MROWS, 256>>>(ph, ln2_w, ln2_b, py);

    gemm_tf32<1><<<dim3(DFF / 128, MROWS / 128), 256, GEMM_SMEM>>>(
        py, w_fc, b_fc, nullptr, pfc, MROWS, DFF, DIM);

    gemm_tf32<2><<<dim3(DIM / 128, MROWS / 128), 256, GEMM_SMEM>>>(
        pfc, w_fc_proj, b_fc_proj, ph, outp, MROWS, DIM, DFF);
}